// round 1
// baseline (speedup 1.0000x reference)
#include <cuda_runtime.h>
#include <math.h>

// Scratch for the intermediate h = x @ W^T + b  (4096 x 4096 fp32 = 64 MB).
// Static __device__ array: the allowed no-alloc scratch mechanism.
__device__ float g_h[4096u * 4096u];

#define BM 128
#define BN 128
#define BK 16
#define TM 8
#define TN 8
#define NTHREADS 256

// C[m][n] = sum_k A[m][k] * B[n][k] + bias[n]   (both operands K-contiguous / NT)
// If DO_COS: C = cos(...) with sign flip where |cos| < 0.01.
template <bool DO_COS>
__global__ __launch_bounds__(NTHREADS, 2)
void gemm_nt_fused(const float* __restrict__ A,
                   const float* __restrict__ Bm,
                   const float* __restrict__ bias,
                   float* __restrict__ C,
                   int M, int N, int K)
{
    __shared__ float As[BK][BM + 4];
    __shared__ float Bs[BK][BN + 4];

    const int tid = threadIdx.x;
    const int ty  = tid >> 4;    // 0..15
    const int tx  = tid & 15;    // 0..15

    const int block_m = blockIdx.y * BM;
    const int block_n = blockIdx.x * BN;

    // Global-load mapping: 128 rows x 16 K-floats per tile = 512 float4;
    // 256 threads -> 2 float4 per matrix per thread.
    const int lrow = tid >> 2;         // 0..63
    const int lcol = (tid & 3) * 4;    // 0,4,8,12

    const float* Aptr = A  + (size_t)block_m * K;
    const float* Bptr = Bm + (size_t)block_n * K;

    float acc[TM][TN];
    #pragma unroll
    for (int i = 0; i < TM; i++)
        #pragma unroll
        for (int j = 0; j < TN; j++)
            acc[i][j] = 0.0f;

    for (int k0 = 0; k0 < K; k0 += BK) {
        #pragma unroll
        for (int r = 0; r < 2; r++) {
            const int row = lrow + r * 64;
            float4 av = *reinterpret_cast<const float4*>(Aptr + (size_t)row * K + k0 + lcol);
            As[lcol + 0][row] = av.x;
            As[lcol + 1][row] = av.y;
            As[lcol + 2][row] = av.z;
            As[lcol + 3][row] = av.w;
            float4 bv = *reinterpret_cast<const float4*>(Bptr + (size_t)row * K + k0 + lcol);
            Bs[lcol + 0][row] = bv.x;
            Bs[lcol + 1][row] = bv.y;
            Bs[lcol + 2][row] = bv.z;
            Bs[lcol + 3][row] = bv.w;
        }
        __syncthreads();

        #pragma unroll
        for (int k = 0; k < BK; k++) {
            float a[TM], b[TN];
            #pragma unroll
            for (int i = 0; i < TM; i++) a[i] = As[k][ty * TM + i];
            #pragma unroll
            for (int j = 0; j < TN; j++) b[j] = Bs[k][tx * TN + j];
            #pragma unroll
            for (int i = 0; i < TM; i++)
                #pragma unroll
                for (int j = 0; j < TN; j++)
                    acc[i][j] = fmaf(a[i], b[j], acc[i][j]);
        }
        __syncthreads();
    }

    // Epilogue: bias (+ optional cos/flip), vectorized float4 stores.
    const int n0 = block_n + tx * TN;
    float4 bias01 = *reinterpret_cast<const float4*>(bias + n0);
    float4 bias23 = *reinterpret_cast<const float4*>(bias + n0 + 4);
    const float bb[TN] = {bias01.x, bias01.y, bias01.z, bias01.w,
                          bias23.x, bias23.y, bias23.z, bias23.w};

    #pragma unroll
    for (int i = 0; i < TM; i++) {
        const int m = block_m + ty * TM + i;
        float out[TN];
        #pragma unroll
        for (int j = 0; j < TN; j++) {
            float v = acc[i][j] + bb[j];
            if (DO_COS) {
                float c = cosf(v);
                if (fabsf(c) < 0.01f) c = -c;
                v = c;
            }
            out[j] = v;
        }
        float4* dst = reinterpret_cast<float4*>(C + (size_t)m * N + n0);
        dst[0] = make_float4(out[0], out[1], out[2], out[3]);
        dst[1] = make_float4(out[4], out[5], out[6], out[7]);
    }
}

extern "C" void kernel_launch(void* const* d_in, const int* in_sizes, int n_in,
                              void* d_out, int out_size)
{
    const float* x      = (const float*)d_in[0];  // [B, D_IN]
    const float* W      = (const float*)d_in[1];  // [D_OUT, D_IN]
    const float* b      = (const float*)d_in[2];  // [D_OUT]
    const float* g      = (const float*)d_in[3];  // [D_OUT, D_OUT]
    const float* g_bias = (const float*)d_in[4];  // [D_OUT]
    float* out          = (float*)d_out;          // [B, D_OUT]

    const int D_OUT = in_sizes[2];                // 4096
    const int D_IN  = in_sizes[1] / D_OUT;        // 4096
    const int B     = in_sizes[0] / D_IN;         // 4096

    float* h = nullptr;
    cudaGetSymbolAddress((void**)&h, g_h);        // not a stream op; capture-safe

    dim3 block(NTHREADS);
    dim3 grid1(D_OUT / BN, B / BM);
    // h = x @ W^T + b
    gemm_nt_fused<false><<<grid1, block>>>(x, W, b, h, B, D_OUT, D_IN);
    // out = flip(cos(h @ g^T + g_bias))
    dim3 grid2(D_OUT / BN, B / BM);
    gemm_nt_fused<true><<<grid2, block>>>(h, g, g_bias, out, B, D_OUT, D_OUT);
}

// round 6
// speedup vs baseline: 2.7222x; 2.7222x over previous
#include <cuda_runtime.h>
#include <cuda_fp16.h>
#include <cstdint>
#include <math.h>

#define DSIZE 4096
#define NELEM ((size_t)DSIZE * (size_t)DSIZE)

// Static __device__ scratch (sanctioned no-alloc mechanism): 6 x 32 MB fp16
__device__ __align__(256) __half g_ah[NELEM];
__device__ __align__(256) __half g_al[NELEM];
__device__ __align__(256) __half g_bh[NELEM];
__device__ __align__(256) __half g_bl[NELEM];
__device__ __align__(256) __half g_hh[NELEM];
__device__ __align__(256) __half g_hl[NELEM];

// ---------------------------------------------------------------- tile config
#define BM 128
#define BN 128
#define BK 32
#define NTHREADS 256
#define STAGES 4
#define NCHUNK (DSIZE / BK)            // 128

#define TILE_BYTES (128 * BK * 2)      // 8192 per operand tile
#define OFF_AH 0
#define OFF_AL 8192
#define OFF_BH 16384
#define OFF_BL 24576
#define STAGE_BYTES 32768
#define SMEM_TOTAL (STAGES * STAGE_BYTES)   // 131072

// ---------------------------------------------------------------- asm helpers
__device__ __forceinline__ uint32_t smem_u32(const void* p) {
    uint32_t a;
    asm("{ .reg .u64 t; cvta.to.shared.u64 t, %1; cvt.u32.u64 %0, t; }" : "=r"(a) : "l"(p));
    return a;
}
#define CP_COMMIT() asm volatile("cp.async.commit_group;" ::: "memory")
#define CP_WAIT(N)  asm volatile("cp.async.wait_group %0;" :: "n"(N) : "memory")

__device__ __forceinline__ void ldsm4(uint32_t* r, uint32_t addr) {
    asm volatile("ldmatrix.sync.aligned.m8n8.x4.shared.b16 {%0,%1,%2,%3}, [%4];"
                 : "=r"(r[0]), "=r"(r[1]), "=r"(r[2]), "=r"(r[3]) : "r"(addr));
}
__device__ __forceinline__ void mma16816(float* d, const uint32_t* a, const uint32_t* b) {
    asm volatile("mma.sync.aligned.m16n8k16.row.col.f32.f16.f16.f32 "
                 "{%0,%1,%2,%3}, {%4,%5,%6,%7}, {%8,%9}, {%0,%1,%2,%3};"
                 : "+f"(d[0]), "+f"(d[1]), "+f"(d[2]), "+f"(d[3])
                 : "r"(a[0]), "r"(a[1]), "r"(a[2]), "r"(a[3]), "r"(b[0]), "r"(b[1]));
}

// Copy one [128 x 32 fp16] tile (64B rows) into XOR-swizzled smem.
// Swizzle: 16B-segment' = seg ^ ((row >> 1) & 3)  — conflict-free for STS.128 + ldmatrix.
__device__ __forceinline__ void load_tile(uint32_t dst, const __half* src,
                                          int row0, int k0, int tid) {
    const char* gbase = reinterpret_cast<const char*>(src + (size_t)row0 * DSIZE + k0);
    #pragma unroll
    for (int t = 0; t < 2; t++) {
        const int i = tid + t * NTHREADS;       // 0..511
        const uint32_t r = (uint32_t)i >> 2;
        const uint32_t seg = (uint32_t)i & 3;
        const uint32_t sw = seg ^ ((r >> 1) & 3);
        asm volatile("cp.async.cg.shared.global [%0], [%1], 16;"
                     :: "r"(dst + r * 64 + sw * 16),
                        "l"(gbase + (size_t)r * (DSIZE * 2) + seg * 16));
    }
}

// ---------------------------------------------------------------- GEMM kernel
// C = (Ah+Al) @ (Bh+Bl)^T + bias, via 3 HMMA products (AlBl dropped, ~2^-22).
// MODE 0: write fp16 hi/lo split of result (feeds second GEMM).
// MODE 1: write flip(cos(result)) as fp32.
template <int MODE>
__global__ __launch_bounds__(NTHREADS)
void gemm_split3(const __half* __restrict__ Ah, const __half* __restrict__ Al,
                 const __half* __restrict__ Bh, const __half* __restrict__ Bl,
                 const float* __restrict__ bias,
                 float* __restrict__ outF,
                 __half* __restrict__ outH, __half* __restrict__ outL)
{
    extern __shared__ __align__(1024) char smem[];
    const uint32_t sb = smem_u32(smem);

    const int tid = threadIdx.x;
    const int lane = tid & 31;
    const int wid = tid >> 5;
    const int warp_m = wid & 3;       // 4 warps along M, 32 rows each
    const int warp_n = wid >> 2;      // 2 warps along N, 64 cols each
    const int bm = blockIdx.y * BM;
    const int bn = blockIdx.x * BN;

    float acc[2][8][4];
    #pragma unroll
    for (int mt = 0; mt < 2; mt++)
        #pragma unroll
        for (int nt = 0; nt < 8; nt++)
            #pragma unroll
            for (int j = 0; j < 4; j++)
                acc[mt][nt][j] = 0.0f;

    // Prologue: fill STAGES-1 pipeline stages
    #pragma unroll
    for (int s = 0; s < STAGES - 1; s++) {
        const uint32_t st = sb + s * STAGE_BYTES;
        load_tile(st + OFF_AH, Ah, bm, s * BK, tid);
        load_tile(st + OFF_AL, Al, bm, s * BK, tid);
        load_tile(st + OFF_BH, Bh, bn, s * BK, tid);
        load_tile(st + OFF_BL, Bl, bn, s * BK, tid);
        CP_COMMIT();
    }

    for (int k = 0; k < NCHUNK; k++) {
        CP_WAIT(STAGES - 2);
        __syncthreads();

        const int kn = k + STAGES - 1;
        if (kn < NCHUNK) {
            const uint32_t st = sb + (kn & (STAGES - 1)) * STAGE_BYTES;
            load_tile(st + OFF_AH, Ah, bm, kn * BK, tid);
            load_tile(st + OFF_AL, Al, bm, kn * BK, tid);
            load_tile(st + OFF_BH, Bh, bn, kn * BK, tid);
            load_tile(st + OFF_BL, Bl, bn, kn * BK, tid);
        }
        CP_COMMIT();   // commit (possibly empty) group to keep wait counts consistent

        const uint32_t sa = sb + (k & (STAGES - 1)) * STAGE_BYTES;

        #pragma unroll
        for (int ks = 0; ks < 2; ks++) {
            // A fragments: 2 m-tiles x (hi, lo)
            uint32_t ah[2][4], al[2][4];
            #pragma unroll
            for (int mt = 0; mt < 2; mt++) {
                const uint32_t row = warp_m * 32 + mt * 16 + (lane & 15);
                const uint32_t seg = ks * 2 + (lane >> 4);
                const uint32_t off = row * 64 + ((seg ^ ((row >> 1) & 3)) << 4);
                ldsm4(ah[mt], sa + OFF_AH + off);
                ldsm4(al[mt], sa + OFF_AL + off);
            }
            // B fragments: 8 n-tiles x (hi, lo); one ldmatrix.x4 covers 2 n-tiles
            uint32_t bh[8][2], bl[8][2];
            #pragma unroll
            for (int p = 0; p < 4; p++) {
                const uint32_t n = warp_n * 64 + p * 16 + ((lane >> 4) << 3) + (lane & 7);
                const uint32_t seg = ks * 2 + ((lane >> 3) & 1);
                const uint32_t off = n * 64 + ((seg ^ ((n >> 1) & 3)) << 4);
                uint32_t th[4], tl[4];
                ldsm4(th, sa + OFF_BH + off);
                ldsm4(tl, sa + OFF_BL + off);
                bh[2 * p][0] = th[0]; bh[2 * p][1] = th[1];
                bh[2 * p + 1][0] = th[2]; bh[2 * p + 1][1] = th[3];
                bl[2 * p][0] = tl[0]; bl[2 * p][1] = tl[1];
                bl[2 * p + 1][0] = tl[2]; bl[2 * p + 1][1] = tl[3];
            }
            // 3-product accumulate
            #pragma unroll
            for (int mt = 0; mt < 2; mt++)
                #pragma unroll
                for (int nt = 0; nt < 8; nt++) {
                    mma16816(acc[mt][nt], ah[mt], bh[nt]);
                    mma16816(acc[mt][nt], ah[mt], bl[nt]);
                    mma16816(acc[mt][nt], al[mt], bh[nt]);
                }
        }
    }

    // ---------------------------------------------------------------- epilogue
    const int g = lane >> 2;
    const int tig = lane & 3;
    #pragma unroll
    for (int mt = 0; mt < 2; mt++) {
        #pragma unroll
        for (int nt = 0; nt < 8; nt++) {
            const int col = bn + warp_n * 64 + nt * 8 + tig * 2;
            const float2 bv = *reinterpret_cast<const float2*>(bias + col);
            const int r0 = bm + warp_m * 32 + mt * 16 + g;
            const float* a = acc[mt][nt];
            float v00 = a[0] + bv.x, v01 = a[1] + bv.y;   // row r0
            float v10 = a[2] + bv.x, v11 = a[3] + bv.y;   // row r0+8
            if (MODE == 1) {
                float c;
                c = cosf(v00); if (fabsf(c) < 0.01f) c = -c; v00 = c;
                c = cosf(v01); if (fabsf(c) < 0.01f) c = -c; v01 = c;
                c = cosf(v10); if (fabsf(c) < 0.01f) c = -c; v10 = c;
                c = cosf(v11); if (fabsf(c) < 0.01f) c = -c; v11 = c;
                *reinterpret_cast<float2*>(outF + (size_t)r0 * DSIZE + col) =
                    make_float2(v00, v01);
                *reinterpret_cast<float2*>(outF + (size_t)(r0 + 8) * DSIZE + col) =
                    make_float2(v10, v11);
            } else {
                const __half h00 = __float2half_rn(v00), h01 = __float2half_rn(v01);
                const __half h10 = __float2half_rn(v10), h11 = __float2half_rn(v11);
                const __half l00 = __float2half_rn(v00 - __half2float(h00));
                const __half l01 = __float2half_rn(v01 - __half2float(h01));
                const __half l10 = __float2half_rn(v10 - __half2float(h10));
                const __half l11 = __float2half_rn(v11 - __half2float(h11));
                *reinterpret_cast<__half2*>(outH + (size_t)r0 * DSIZE + col) =
                    __halves2half2(h00, h01);
                *reinterpret_cast<__half2*>(outH + (size_t)(r0 + 8) * DSIZE + col) =
                    __halves2half2(h10, h11);
                *reinterpret_cast<__half2*>(outL + (size_t)r0 * DSIZE + col) =
                    __halves2half2(l00, l01);
                *reinterpret_cast<__half2*>(outL + (size_t)(r0 + 8) * DSIZE + col) =
                    __halves2half2(l10, l11);
            }
        }
    }
}

// ---------------------------------------------------------------- fp32 -> fp16 hi/lo
__global__ __launch_bounds__(256)
void split_fp32(const float* __restrict__ in, __half* __restrict__ hi,
                __half* __restrict__ lo)
{
    const size_t i = ((size_t)blockIdx.x * 256 + threadIdx.x) * 4;
    const float4 v = *reinterpret_cast<const float4*>(in + i);
    const __half h0 = __float2half_rn(v.x), h1 = __float2half_rn(v.y);
    const __half h2 = __float2half_rn(v.z), h3 = __float2half_rn(v.w);
    const __half l0 = __float2half_rn(v.x - __half2float(h0));
    const __half l1 = __float2half_rn(v.y - __half2float(h1));
    const __half l2 = __float2half_rn(v.z - __half2float(h2));
    const __half l3 = __float2half_rn(v.w - __half2float(h3));
    reinterpret_cast<__half2*>(hi + i)[0] = __halves2half2(h0, h1);
    reinterpret_cast<__half2*>(hi + i)[1] = __halves2half2(h2, h3);
    reinterpret_cast<__half2*>(lo + i)[0] = __halves2half2(l0, l1);
    reinterpret_cast<__half2*>(lo + i)[1] = __halves2half2(l2, l3);
}

// ---------------------------------------------------------------- launch
extern "C" void kernel_launch(void* const* d_in, const int* in_sizes, int n_in,
                              void* d_out, int out_size)
{
    const float* x      = (const float*)d_in[0];
    const float* W      = (const float*)d_in[1];
    const float* b      = (const float*)d_in[2];
    const float* g      = (const float*)d_in[3];
    const float* g_bias = (const float*)d_in[4];
    float* out          = (float*)d_out;

    __half *ah, *al, *bh, *bl, *hh, *hl;
    cudaGetSymbolAddress((void**)&ah, g_ah);
    cudaGetSymbolAddress((void**)&al, g_al);
    cudaGetSymbolAddress((void**)&bh, g_bh);
    cudaGetSymbolAddress((void**)&bl, g_bl);
    cudaGetSymbolAddress((void**)&hh, g_hh);
    cudaGetSymbolAddress((void**)&hl, g_hl);

    cudaFuncSetAttribute(gemm_split3<0>, cudaFuncAttributeMaxDynamicSharedMemorySize, SMEM_TOTAL);
    cudaFuncSetAttribute(gemm_split3<1>, cudaFuncAttributeMaxDynamicSharedMemorySize, SMEM_TOTAL);

    const int sgrid = (int)(NELEM / 4 / 256);        // 16384
    const dim3 ggrid(DSIZE / BN, DSIZE / BM);        // (32, 32)

    split_fp32<<<sgrid, 256>>>(x, ah, al);
    split_fp32<<<sgrid, 256>>>(W, bh, bl);
    // h = x @ W^T + b, written directly as fp16 hi/lo split
    gemm_split3<0><<<ggrid, NTHREADS, SMEM_TOTAL>>>(ah, al, bh, bl, b,
                                                    nullptr, hh, hl);
    // reuse bh/bl for g (stream-ordered after gemm1 finished reading them)
    split_fp32<<<sgrid, 256>>>(g, bh, bl);
    // out = flip(cos(h @ g^T + g_bias))
    gemm_split3<1><<<ggrid, NTHREADS, SMEM_TOTAL>>>(hh, hl, bh, bl, g_bias,
                                                    out, nullptr, nullptr);
}